// round 1
// baseline (speedup 1.0000x reference)
#include <cuda_runtime.h>
#include <math.h>

// Problem constants (fixed shapes — no bounds checks needed)
#define SEQ   1024
#define DIM   1024
#define NB    4
#define NH    16
#define HD    64
#define MROWS (NB * SEQ)          // 4096
#define ATT_SCALE 0.03125f        // 1/sqrt(1024)
#define ATT_CLIP  10000.0f
#define LN_EPS    1e-5f

// ---------------------------------------------------------------------------
// Scratch (device globals; allocation is forbidden)
// ---------------------------------------------------------------------------
__device__ float g_Qn[(size_t)MROWS * DIM];
__device__ float g_Kn[(size_t)MROWS * DIM];
__device__ float g_q [(size_t)MROWS * DIM];
__device__ float g_k [(size_t)MROWS * DIM];
__device__ float g_v [(size_t)MROWS * DIM];
__device__ float g_O [(size_t)MROWS * DIM];
__device__ float g_X [(size_t)MROWS * DIM];

// ---------------------------------------------------------------------------
// LayerNorm over last dim (1024). One CTA per row, 256 threads, 4 elems/thread.
// ---------------------------------------------------------------------------
__global__ void __launch_bounds__(256) ln_kernel(const float* __restrict__ in,
                                                 float* __restrict__ out,
                                                 const float* __restrict__ gg,
                                                 const float* __restrict__ bb) {
    const int row = blockIdx.x;
    const int t = threadIdx.x;
    const float4* x4 = (const float4*)(in + (size_t)row * DIM);
    float4* y4 = (float4*)(out + (size_t)row * DIM);

    float4 xv = x4[t];
    float s  = xv.x + xv.y + xv.z + xv.w;
    float s2 = xv.x * xv.x + xv.y * xv.y + xv.z * xv.z + xv.w * xv.w;
#pragma unroll
    for (int o = 16; o > 0; o >>= 1) {
        s  += __shfl_xor_sync(0xffffffffu, s, o);
        s2 += __shfl_xor_sync(0xffffffffu, s2, o);
    }
    __shared__ float ws[8], ws2[8];
    __shared__ float s_mean, s_inv;
    const int wid = t >> 5, lane = t & 31;
    if (lane == 0) { ws[wid] = s; ws2[wid] = s2; }
    __syncthreads();
    if (t == 0) {
        float S = 0.f, S2 = 0.f;
#pragma unroll
        for (int i = 0; i < 8; i++) { S += ws[i]; S2 += ws2[i]; }
        const float mean = S * (1.0f / DIM);
        const float var  = S2 * (1.0f / DIM) - mean * mean;
        s_mean = mean;
        s_inv  = rsqrtf(var + LN_EPS);
    }
    __syncthreads();
    const float mean = s_mean, inv = s_inv;
    const float4 gv = ((const float4*)gg)[t];
    const float4 bv = ((const float4*)bb)[t];
    float4 r;
    r.x = (xv.x - mean) * inv * gv.x + bv.x;
    r.y = (xv.y - mean) * inv * gv.y + bv.y;
    r.z = (xv.z - mean) * inv * gv.z + bv.z;
    r.w = (xv.w - mean) * inv * gv.w + bv.w;
    y4[t] = r;
}

// ---------------------------------------------------------------------------
// NT GEMM: C[m,n] = sum_k A[m,k] * B[n,k].  A:[4096,1024], B:[1024,1024].
// 128x128 block tile, BK=8, 256 threads, 8x8 per-thread microtile.
// op=0: plain store.  op=1: C = X + gelu_exact(acc)  (X same layout as C).
// ---------------------------------------------------------------------------
__device__ __forceinline__ float gelu_exact(float x) {
    return 0.5f * x * (1.0f + erff(x * 0.70710678118654752f));
}

__global__ void __launch_bounds__(256) gemm_nt(const float* __restrict__ A,
                                               const float* __restrict__ B,
                                               float* __restrict__ C,
                                               const float* __restrict__ X,
                                               int op) {
    __shared__ float As[8][128];
    __shared__ float Bs[8][128];
    const int t  = threadIdx.x;
    const int bm = blockIdx.y * 128;
    const int bn = blockIdx.x * 128;
    const int ty = t >> 4, tx = t & 15;
    const int lr = t >> 1;
    const int lc = (t & 1) * 4;

    const float* Ap = A + (size_t)(bm + lr) * DIM + lc;
    const float* Bp = B + (size_t)(bn + lr) * DIM + lc;

    float acc[8][8];
#pragma unroll
    for (int i = 0; i < 8; i++)
#pragma unroll
        for (int j = 0; j < 8; j++) acc[i][j] = 0.f;

    for (int k0 = 0; k0 < DIM; k0 += 8) {
        const float4 av = *(const float4*)(Ap + k0);
        const float4 bv = *(const float4*)(Bp + k0);
        As[lc + 0][lr] = av.x; As[lc + 1][lr] = av.y;
        As[lc + 2][lr] = av.z; As[lc + 3][lr] = av.w;
        Bs[lc + 0][lr] = bv.x; Bs[lc + 1][lr] = bv.y;
        Bs[lc + 2][lr] = bv.z; Bs[lc + 3][lr] = bv.w;
        __syncthreads();
#pragma unroll
        for (int kk = 0; kk < 8; kk++) {
            float a[8], b[8];
            *(float4*)&a[0] = *(const float4*)&As[kk][ty * 8];
            *(float4*)&a[4] = *(const float4*)&As[kk][ty * 8 + 4];
            *(float4*)&b[0] = *(const float4*)&Bs[kk][tx * 8];
            *(float4*)&b[4] = *(const float4*)&Bs[kk][tx * 8 + 4];
#pragma unroll
            for (int i = 0; i < 8; i++)
#pragma unroll
                for (int j = 0; j < 8; j++)
                    acc[i][j] = fmaf(a[i], b[j], acc[i][j]);
        }
        __syncthreads();
    }

#pragma unroll
    for (int i = 0; i < 8; i++) {
        const int row = bm + ty * 8 + i;
#pragma unroll
        for (int j = 0; j < 8; j += 4) {
            const int col = bn + tx * 8 + j;
            float4 o;
            if (op) {
                const float4 xv = *(const float4*)(X + (size_t)row * DIM + col);
                o.x = xv.x + gelu_exact(acc[i][j + 0]);
                o.y = xv.y + gelu_exact(acc[i][j + 1]);
                o.z = xv.z + gelu_exact(acc[i][j + 2]);
                o.w = xv.w + gelu_exact(acc[i][j + 3]);
            } else {
                o = make_float4(acc[i][j], acc[i][j + 1], acc[i][j + 2], acc[i][j + 3]);
            }
            *(float4*)(C + (size_t)row * DIM + col) = o;
        }
    }
}

// ---------------------------------------------------------------------------
// Flash attention (per batch b, head h): online softmax.
// CTA = 64 q-rows; loop k in tiles of 32. 128 threads: ty(16) x tx(8).
// S tile: thread owns 4 q-rows x 4 k-cols. O acc: 4 q-rows x 8 d-cols.
// Layout: q/k/v/O are [4096, 1024] with head h at cols [h*64, h*64+64).
// ---------------------------------------------------------------------------
__global__ void __launch_bounds__(128) attn_kernel(const float* __restrict__ Qp,
                                                   const float* __restrict__ Kp,
                                                   const float* __restrict__ Vp,
                                                   float* __restrict__ Op) {
    __shared__ float qs[64][65];
    __shared__ float ks[32][65];
    __shared__ float vs[32][65];
    __shared__ float ps[64][33];

    const int t  = threadIdx.x;
    const int ty = t >> 3;   // 0..15  -> q rows ty*4 .. ty*4+3
    const int tx = t & 7;    // 0..7   -> S cols tx*4.. / O d-cols tx*8..
    const int q0 = blockIdx.x * 64;
    const size_t base = (size_t)blockIdx.z * ((size_t)SEQ * DIM) + (size_t)blockIdx.y * HD;

    // Load q tile [64 x 64]
#pragma unroll
    for (int i = t; i < 64 * 16; i += 128) {
        const int r = i >> 4, c = (i & 15) * 4;
        const float4 v = *(const float4*)(Qp + base + (size_t)(q0 + r) * DIM + c);
        qs[r][c] = v.x; qs[r][c + 1] = v.y; qs[r][c + 2] = v.z; qs[r][c + 3] = v.w;
    }

    float acc[4][8];
    float m_i[4], l_i[4];
#pragma unroll
    for (int i = 0; i < 4; i++) {
        m_i[i] = -1e30f; l_i[i] = 0.f;
#pragma unroll
        for (int j = 0; j < 8; j++) acc[i][j] = 0.f;
    }

    for (int k0 = 0; k0 < SEQ; k0 += 32) {
        __syncthreads();  // prev PV done (and qs visible on first iter)
        // Load k,v tiles [32 x 64]
#pragma unroll
        for (int i = t; i < 32 * 16; i += 128) {
            const int r = i >> 4, c = (i & 15) * 4;
            const size_t off = base + (size_t)(k0 + r) * DIM + c;
            const float4 kv = *(const float4*)(Kp + off);
            const float4 vv = *(const float4*)(Vp + off);
            ks[r][c] = kv.x; ks[r][c + 1] = kv.y; ks[r][c + 2] = kv.z; ks[r][c + 3] = kv.w;
            vs[r][c] = vv.x; vs[r][c + 1] = vv.y; vs[r][c + 2] = vv.z; vs[r][c + 3] = vv.w;
        }
        __syncthreads();

        // S = q @ k^T  (4x4 per thread)
        float s[4][4];
#pragma unroll
        for (int i = 0; i < 4; i++)
#pragma unroll
            for (int j = 0; j < 4; j++) s[i][j] = 0.f;
#pragma unroll 8
        for (int d = 0; d < 64; d++) {
            float a[4], b[4];
#pragma unroll
            for (int i = 0; i < 4; i++) a[i] = qs[ty * 4 + i][d];
#pragma unroll
            for (int j = 0; j < 4; j++) b[j] = ks[tx * 4 + j][d];
#pragma unroll
            for (int i = 0; i < 4; i++)
#pragma unroll
                for (int j = 0; j < 4; j++) s[i][j] = fmaf(a[i], b[j], s[i][j]);
        }

        // scale + clip + online softmax update
#pragma unroll
        for (int i = 0; i < 4; i++) {
#pragma unroll
            for (int j = 0; j < 4; j++)
                s[i][j] = fminf(fmaxf(s[i][j] * ATT_SCALE, -ATT_CLIP), ATT_CLIP);
            float rm = fmaxf(fmaxf(s[i][0], s[i][1]), fmaxf(s[i][2], s[i][3]));
            rm = fmaxf(rm, __shfl_xor_sync(0xffffffffu, rm, 1, 8));
            rm = fmaxf(rm, __shfl_xor_sync(0xffffffffu, rm, 2, 8));
            rm = fmaxf(rm, __shfl_xor_sync(0xffffffffu, rm, 4, 8));
            const float mn = fmaxf(m_i[i], rm);
            const float alpha = __expf(m_i[i] - mn);
            float rs = 0.f;
#pragma unroll
            for (int j = 0; j < 4; j++) {
                s[i][j] = __expf(s[i][j] - mn);
                rs += s[i][j];
            }
            rs += __shfl_xor_sync(0xffffffffu, rs, 1, 8);
            rs += __shfl_xor_sync(0xffffffffu, rs, 2, 8);
            rs += __shfl_xor_sync(0xffffffffu, rs, 4, 8);
            l_i[i] = l_i[i] * alpha + rs;
            m_i[i] = mn;
#pragma unroll
            for (int j = 0; j < 8; j++) acc[i][j] *= alpha;
#pragma unroll
            for (int j = 0; j < 4; j++) ps[ty * 4 + i][tx * 4 + j] = s[i][j];
        }
        __syncthreads();

        // O += P @ V   (acc[i][j] over d-cols tx*8+j)
#pragma unroll 4
        for (int kk = 0; kk < 32; kk++) {
            float p[4], v[8];
#pragma unroll
            for (int i = 0; i < 4; i++) p[i] = ps[ty * 4 + i][kk];
#pragma unroll
            for (int j = 0; j < 8; j++) v[j] = vs[kk][tx * 8 + j];
#pragma unroll
            for (int i = 0; i < 4; i++)
#pragma unroll
                for (int j = 0; j < 8; j++)
                    acc[i][j] = fmaf(p[i], v[j], acc[i][j]);
        }
    }

    // normalize + write
#pragma unroll
    for (int i = 0; i < 4; i++) {
        const float inv = 1.0f / l_i[i];
        float4 o0, o1;
        o0.x = acc[i][0] * inv; o0.y = acc[i][1] * inv;
        o0.z = acc[i][2] * inv; o0.w = acc[i][3] * inv;
        o1.x = acc[i][4] * inv; o1.y = acc[i][5] * inv;
        o1.z = acc[i][6] * inv; o1.w = acc[i][7] * inv;
        const size_t orow = base + (size_t)(q0 + ty * 4 + i) * DIM + tx * 8;
        *(float4*)(Op + orow)     = o0;
        *(float4*)(Op + orow + 4) = o1;
    }
}

// ---------------------------------------------------------------------------
// Launch
// ---------------------------------------------------------------------------
extern "C" void kernel_launch(void* const* d_in, const int* in_sizes, int n_in,
                              void* d_out, int out_size) {
    (void)in_sizes; (void)n_in; (void)out_size;
    const float* Q     = (const float*)d_in[0];
    const float* K     = (const float*)d_in[1];
    const float* V     = (const float*)d_in[2];
    const float* Wq    = (const float*)d_in[3];
    const float* Wk    = (const float*)d_in[4];
    const float* Wv    = (const float*)d_in[5];
    const float* Wo    = (const float*)d_in[6];
    const float* pre_g = (const float*)d_in[7];
    const float* pre_b = (const float*)d_in[8];
    const float* ln_g  = (const float*)d_in[9];
    const float* ln_b  = (const float*)d_in[10];
    float* out = (float*)d_out;

    float *qn, *kn, *qp, *kp, *vp, *op, *xp;
    cudaGetSymbolAddress((void**)&qn, g_Qn);
    cudaGetSymbolAddress((void**)&kn, g_Kn);
    cudaGetSymbolAddress((void**)&qp, g_q);
    cudaGetSymbolAddress((void**)&kp, g_k);
    cudaGetSymbolAddress((void**)&vp, g_v);
    cudaGetSymbolAddress((void**)&op, g_O);
    cudaGetSymbolAddress((void**)&xp, g_X);

    const dim3 ggrid(DIM / 128, MROWS / 128);

    ln_kernel<<<MROWS, 256>>>(Q, qn, pre_g, pre_b);
    ln_kernel<<<MROWS, 256>>>(K, kn, pre_g, pre_b);
    gemm_nt<<<ggrid, 256>>>(qn, Wq, qp, nullptr, 0);
    gemm_nt<<<ggrid, 256>>>(kn, Wk, kp, nullptr, 0);
    gemm_nt<<<ggrid, 256>>>(V,  Wv, vp, nullptr, 0);
    attn_kernel<<<dim3(SEQ / 64, NH, NB), 128>>>(qp, kp, vp, op);
    ln_kernel<<<MROWS, 256>>>(op, xp, ln_g, ln_b);
    gemm_nt<<<ggrid, 256>>>(xp, Wo, out, xp, 1);
}

// round 4
// speedup vs baseline: 1.6133x; 1.6133x over previous
#include <cuda_runtime.h>
#include <cuda_bf16.h>
#include <math.h>
#include <stdint.h>

// Problem constants
#define SEQ   1024
#define DIM   1024
#define NB    4
#define NH    16
#define HD    64
#define MROWS (NB * SEQ)          // 4096
#define ATT_SCALE 0.03125f        // 1/sqrt(1024)
#define ATT_CLIP  10000.0f
#define LN_EPS    1e-5f

// ---------------------------------------------------------------------------
// Scratch (device globals; allocation is forbidden)
// ---------------------------------------------------------------------------
__device__ __nv_bfloat16 g_Qh[(size_t)MROWS * DIM];
__device__ __nv_bfloat16 g_Ql[(size_t)MROWS * DIM];
__device__ __nv_bfloat16 g_Kh[(size_t)MROWS * DIM];
__device__ __nv_bfloat16 g_Kl[(size_t)MROWS * DIM];
__device__ __nv_bfloat16 g_Vh[(size_t)MROWS * DIM];
__device__ __nv_bfloat16 g_Vl[(size_t)MROWS * DIM];
__device__ __nv_bfloat16 g_Xh[(size_t)MROWS * DIM];
__device__ __nv_bfloat16 g_Xl[(size_t)MROWS * DIM];
__device__ __nv_bfloat16 g_Wqh[(size_t)DIM * DIM];
__device__ __nv_bfloat16 g_Wql[(size_t)DIM * DIM];
__device__ __nv_bfloat16 g_Wkh[(size_t)DIM * DIM];
__device__ __nv_bfloat16 g_Wkl[(size_t)DIM * DIM];
__device__ __nv_bfloat16 g_Wvh[(size_t)DIM * DIM];
__device__ __nv_bfloat16 g_Wvl[(size_t)DIM * DIM];
__device__ __nv_bfloat16 g_Woh[(size_t)DIM * DIM];
__device__ __nv_bfloat16 g_Wol[(size_t)DIM * DIM];
__device__ float g_q [(size_t)MROWS * DIM];
__device__ float g_k [(size_t)MROWS * DIM];
__device__ float g_v [(size_t)MROWS * DIM];
__device__ float g_O [(size_t)MROWS * DIM];
__device__ float g_X [(size_t)MROWS * DIM];

// ---------------------------------------------------------------------------
// Helpers
// ---------------------------------------------------------------------------
__device__ __forceinline__ uint32_t smem_u32(const void* p) {
    uint32_t a;
    asm("{ .reg .u64 t; cvta.to.shared.u64 t, %1; cvt.u32.u64 %0, t; }" : "=r"(a) : "l"(p));
    return a;
}

__device__ __forceinline__ void ldsm4(uint32_t* r, uint32_t addr) {
    asm volatile("ldmatrix.sync.aligned.m8n8.x4.shared.b16 {%0,%1,%2,%3}, [%4];"
                 : "=r"(r[0]), "=r"(r[1]), "=r"(r[2]), "=r"(r[3]) : "r"(addr));
}

__device__ __forceinline__ void mma16816(float* c, const uint32_t* a, const uint32_t* b) {
    asm volatile(
        "mma.sync.aligned.m16n8k16.row.col.f32.bf16.bf16.f32 "
        "{%0,%1,%2,%3}, {%4,%5,%6,%7}, {%8,%9}, {%0,%1,%2,%3};"
        : "+f"(c[0]), "+f"(c[1]), "+f"(c[2]), "+f"(c[3])
        : "r"(a[0]), "r"(a[1]), "r"(a[2]), "r"(a[3]), "r"(b[0]), "r"(b[1]));
}

__device__ __forceinline__ void cp16(uint32_t dst, const void* src) {
    asm volatile("cp.async.cg.shared.global [%0], [%1], 16;" :: "r"(dst), "l"(src));
}

__device__ __forceinline__ float gelu_exact(float x) {
    return 0.5f * x * (1.0f + erff(x * 0.70710678118654752f));
}

__device__ __forceinline__ void split_bf16(float a, __nv_bfloat16& h, __nv_bfloat16& l) {
    h = __float2bfloat16(a);
    l = __float2bfloat16(a - __bfloat162float(h));
}

// ---------------------------------------------------------------------------
// LayerNorm -> split bf16 (hi/lo) + optional fp32 copy of the normalized row.
// One CTA per row, 256 threads, 4 elems/thread.
// ---------------------------------------------------------------------------
__global__ void __launch_bounds__(256) ln_split_kernel(const float* __restrict__ in,
                                                       __nv_bfloat16* __restrict__ oh,
                                                       __nv_bfloat16* __restrict__ ol,
                                                       float* __restrict__ outf,
                                                       const float* __restrict__ gg,
                                                       const float* __restrict__ bb) {
    const int row = blockIdx.x;
    const int t = threadIdx.x;
    const float4* x4 = (const float4*)(in + (size_t)row * DIM);

    float4 xv = x4[t];
    float s  = xv.x + xv.y + xv.z + xv.w;
    float s2 = xv.x * xv.x + xv.y * xv.y + xv.z * xv.z + xv.w * xv.w;
#pragma unroll
    for (int o = 16; o > 0; o >>= 1) {
        s  += __shfl_xor_sync(0xffffffffu, s, o);
        s2 += __shfl_xor_sync(0xffffffffu, s2, o);
    }
    __shared__ float ws[8], ws2[8];
    __shared__ float s_mean, s_inv;
    const int wid = t >> 5, lane = t & 31;
    if (lane == 0) { ws[wid] = s; ws2[wid] = s2; }
    __syncthreads();
    if (t == 0) {
        float S = 0.f, S2 = 0.f;
#pragma unroll
        for (int i = 0; i < 8; i++) { S += ws[i]; S2 += ws2[i]; }
        const float mean = S * (1.0f / DIM);
        const float var  = S2 * (1.0f / DIM) - mean * mean;
        s_mean = mean;
        s_inv  = rsqrtf(var + LN_EPS);
    }
    __syncthreads();
    const float mean = s_mean, inv = s_inv;
    const float4 gv = ((const float4*)gg)[t];
    const float4 bv = ((const float4*)bb)[t];
    float r[4];
    r[0] = (xv.x - mean) * inv * gv.x + bv.x;
    r[1] = (xv.y - mean) * inv * gv.y + bv.y;
    r[2] = (xv.z - mean) * inv * gv.z + bv.z;
    r[3] = (xv.w - mean) * inv * gv.w + bv.w;
    __nv_bfloat16 h[4], l[4];
#pragma unroll
    for (int i = 0; i < 4; i++) split_bf16(r[i], h[i], l[i]);
    *(uint2*)(oh + (size_t)row * DIM + t * 4) = *(uint2*)h;
    *(uint2*)(ol + (size_t)row * DIM + t * 4) = *(uint2*)l;
    if (outf) ((float4*)(outf + (size_t)row * DIM))[t] = *(float4*)r;
}

// ---------------------------------------------------------------------------
// fp32 -> split bf16 elementwise (4 elems/thread)
// ---------------------------------------------------------------------------
__global__ void __launch_bounds__(256) f2bf_split_kernel(const float* __restrict__ src,
                                                         __nv_bfloat16* __restrict__ dh,
                                                         __nv_bfloat16* __restrict__ dl) {
    const int i = blockIdx.x * 256 + threadIdx.x;
    const float4 v = ((const float4*)src)[i];
    __nv_bfloat16 h[4], l[4];
    split_bf16(v.x, h[0], l[0]);
    split_bf16(v.y, h[1], l[1]);
    split_bf16(v.z, h[2], l[2]);
    split_bf16(v.w, h[3], l[3]);
    *(uint2*)(dh + (size_t)i * 4) = *(uint2*)h;
    *(uint2*)(dl + (size_t)i * 4) = *(uint2*)l;
}

// ---------------------------------------------------------------------------
// Split-bf16 NT GEMM via mma.sync: C = Ah*Bh^T + Ah*Bl^T + Al*Bh^T (fp32 acc)
// A:[4096,1024], B:[1024,1024].  CTA 128x128, BK=32, 3-stage cp.async.
// 256 threads; warp grid 2(m) x 4(n); warp tile 64x32.
// SMEM/stage: 4 tiles (Ah,Al,Bh,Bl) of 128 rows x 64B; swizzle kc ^= (r>>1)&3.
// op=0: plain store.  op=1: C = X + gelu(acc).
// ---------------------------------------------------------------------------
#define GBM 128
#define GBN 128
#define GBK 32
#define GNS (DIM / GBK)          // 32 k-stages
#define TILEB (128 * 64)         // 8192 bytes per tile
#define STGB  (4 * TILEB)        // 32768 bytes per stage
#define GSMEM (3 * STGB)         // 98304

__global__ void __launch_bounds__(256, 1) gemm_mma3(const __nv_bfloat16* __restrict__ Ah,
                                                    const __nv_bfloat16* __restrict__ Al,
                                                    const __nv_bfloat16* __restrict__ Bh,
                                                    const __nv_bfloat16* __restrict__ Bl,
                                                    float* __restrict__ C,
                                                    const float* __restrict__ X,
                                                    int op) {
    extern __shared__ __align__(128) unsigned char smem[];
    const uint32_t base = smem_u32(smem);

    const int tid  = threadIdx.x;
    const int wid  = tid >> 5;
    const int lane = tid & 31;
    const int bm = blockIdx.y * GBM;
    const int bn = blockIdx.x * GBN;

    const __nv_bfloat16* gAh = Ah + (size_t)bm * DIM;
    const __nv_bfloat16* gAl = Al + (size_t)bm * DIM;
    const __nv_bfloat16* gBh = Bh + (size_t)bn * DIM;
    const __nv_bfloat16* gBl = Bl + (size_t)bn * DIM;

    auto issue_stage = [&](int s, int buf) {
        const uint32_t st = base + (uint32_t)buf * STGB;
#pragma unroll
        for (int i = 0; i < 2; i++) {
            const int id = tid + i * 256;
            const int r  = id >> 2;
            const int kc = id & 3;
            const uint32_t off = (uint32_t)r * 64 + (uint32_t)(kc ^ ((r >> 1) & 3)) * 16;
            const size_t go = (size_t)r * DIM + s * GBK + kc * 8;
            cp16(st + off,              gAh + go);
            cp16(st + TILEB + off,      gAl + go);
            cp16(st + 2 * TILEB + off,  gBh + go);
            cp16(st + 3 * TILEB + off,  gBl + go);
        }
        asm volatile("cp.async.commit_group;" ::: "memory");
    };

    // warp tiling
    const int wm = wid >> 2;          // 0..1 -> rows wm*64
    const int wn = wid & 3;           // 0..3 -> cols wn*32

    // ldmatrix per-lane addressing (within a tile)
    const int rA  = wm * 64 + (lane & 15);            // + mi*16
    const int kcA = lane >> 4;                        // + k16*2
    const uint32_t aRowOff = (uint32_t)rA * 64;
    const int aSw = (rA >> 1) & 3;

    const int rB  = wn * 32 + (lane & 7) + ((lane >> 4) << 3);  // + nb*16
    const int kcB = (lane >> 3) & 1;
    const uint32_t bRowOff = (uint32_t)rB * 64;
    const int bSw = (rB >> 1) & 3;

    float acc[4][4][4];
#pragma unroll
    for (int mi = 0; mi < 4; mi++)
#pragma unroll
        for (int ni = 0; ni < 4; ni++)
#pragma unroll
            for (int j = 0; j < 4; j++) acc[mi][ni][j] = 0.f;

    issue_stage(0, 0);
    issue_stage(1, 1);

    for (int s = 0; s < GNS; s++) {
        if (s == GNS - 1) asm volatile("cp.async.wait_group 0;" ::: "memory");
        else              asm volatile("cp.async.wait_group 1;" ::: "memory");
        __syncthreads();
        if (s + 2 < GNS) issue_stage(s + 2, (s + 2) % 3);

        const uint32_t st = base + (uint32_t)(s % 3) * STGB;
        const uint32_t aTh = st;
        const uint32_t aTl = st + TILEB;
        const uint32_t bTh = st + 2 * TILEB;
        const uint32_t bTl = st + 3 * TILEB;

#pragma unroll
        for (int k16 = 0; k16 < 2; k16++) {
            const uint32_t kca = (uint32_t)((k16 * 2 + kcA) ^ aSw) * 16;
            const uint32_t kcb = (uint32_t)((k16 * 2 + kcB) ^ bSw) * 16;
            uint32_t ah[4][4], al[4][4], bh[2][4], bl[2][4];
#pragma unroll
            for (int mi = 0; mi < 4; mi++) {
                ldsm4(ah[mi], aTh + aRowOff + mi * 1024 + kca);
                ldsm4(al[mi], aTl + aRowOff + mi * 1024 + kca);
            }
#pragma unroll
            for (int nb = 0; nb < 2; nb++) {
                ldsm4(bh[nb], bTh + bRowOff + nb * 1024 + kcb);
                ldsm4(bl[nb], bTl + bRowOff + nb * 1024 + kcb);
            }
#pragma unroll
            for (int mi = 0; mi < 4; mi++)
#pragma unroll
                for (int ni = 0; ni < 4; ni++) {
                    mma16816(acc[mi][ni], ah[mi], &bh[ni >> 1][(ni & 1) * 2]);
                    mma16816(acc[mi][ni], ah[mi], &bl[ni >> 1][(ni & 1) * 2]);
                    mma16816(acc[mi][ni], al[mi], &bh[ni >> 1][(ni & 1) * 2]);
                }
        }
    }

    // Epilogue
    const int gid = lane >> 2;
    const int tig = lane & 3;
#pragma unroll
    for (int mi = 0; mi < 4; mi++) {
        const int row0 = bm + wm * 64 + mi * 16 + gid;
#pragma unroll
        for (int ni = 0; ni < 4; ni++) {
            const int col = bn + wn * 32 + ni * 8 + tig * 2;
            float* p0 = C + (size_t)row0 * DIM + col;
            float* p1 = C + (size_t)(row0 + 8) * DIM + col;
            float v0 = acc[mi][ni][0], v1 = acc[mi][ni][1];
            float v2 = acc[mi][ni][2], v3 = acc[mi][ni][3];
            if (op) {
                const float2 xa = *(const float2*)(X + (size_t)row0 * DIM + col);
                const float2 xb = *(const float2*)(X + (size_t)(row0 + 8) * DIM + col);
                v0 = xa.x + gelu_exact(v0);
                v1 = xa.y + gelu_exact(v1);
                v2 = xb.x + gelu_exact(v2);
                v3 = xb.y + gelu_exact(v3);
            }
            *(float2*)p0 = make_float2(v0, v1);
            *(float2*)p1 = make_float2(v2, v3);
        }
    }
}

// ---------------------------------------------------------------------------
// Flash attention (fp32 SIMT)
// ---------------------------------------------------------------------------
__global__ void __launch_bounds__(128) attn_kernel(const float* __restrict__ Qp,
                                                   const float* __restrict__ Kp,
                                                   const float* __restrict__ Vp,
                                                   float* __restrict__ Op) {
    __shared__ float qs[64][65];
    __shared__ float ks[32][65];
    __shared__ float vs[32][65];
    __shared__ float ps[64][33];

    const int t  = threadIdx.x;
    const int ty = t >> 3;
    const int tx = t & 7;
    const int q0 = blockIdx.x * 64;
    const size_t base = (size_t)blockIdx.z * ((size_t)SEQ * DIM) + (size_t)blockIdx.y * HD;

#pragma unroll
    for (int i = t; i < 64 * 16; i += 128) {
        const int r = i >> 4, c = (i & 15) * 4;
        const float4 v = *(const float4*)(Qp + base + (size_t)(q0 + r) * DIM + c);
        qs[r][c] = v.x; qs[r][c + 1] = v.y; qs[r][c + 2] = v.z; qs[r][c + 3] = v.w;
    }

    float acc[4][8];
    float m_i[4], l_i[4];
#pragma unroll
    for (int i = 0; i < 4; i++) {
        m_i[i] = -1e30f; l_i[i] = 0.f;
#pragma unroll
        for (int j = 0; j < 8; j++) acc[i][j] = 0.f;
    }

    for (int k0 = 0; k0 < SEQ; k0 += 32) {
        __syncthreads();
#pragma unroll
        for (int i = t; i < 32 * 16; i += 128) {
            const int r = i >> 4, c = (i & 15) * 4;
            const size_t off = base + (size_t)(k0 + r) * DIM + c;
            const float4 kv = *(const float4*)(Kp + off);
            const float4 vv = *(const float4*)(Vp + off);
            ks[r][c] = kv.x; ks[r][c + 1] = kv.y; ks[r][c + 2] = kv.z; ks[r][c + 3] = kv.w;
            vs[r][c] = vv.x; vs[r][c + 1] = vv.y; vs[r][c + 2] = vv.z; vs[r][c + 3] = vv.w;
        }
        __syncthreads();

        float s[4][4];
#pragma unroll
        for (int i = 0; i < 4; i++)
#pragma unroll
            for (int j = 0; j < 4; j++) s[i][j] = 0.f;
#pragma unroll 8
        for (int d = 0; d < 64; d++) {
            float a[4], b[4];
#pragma unroll
            for (int i = 0; i < 4; i++) a[i] = qs[ty * 4 + i][d];
#pragma unroll
            for (int j = 0; j < 4; j++) b[j] = ks[tx * 4 + j][d];
#pragma unroll
            for (int i = 0; i < 4; i++)
#pragma unroll
                for (int j = 0; j < 4; j++) s[i][j] = fmaf(a[i], b[j], s[i][j]);
        }

#pragma unroll
        for (int i = 0; i < 4; i++) {
#pragma unroll
            for (int j = 0; j < 4; j++)
                s[i][j] = fminf(fmaxf(s[i][j] * ATT_SCALE, -ATT_CLIP), ATT_CLIP);
            float rm = fmaxf(fmaxf(s[i][0], s[i][1]), fmaxf(s[i][2], s[i][3]));
            rm = fmaxf(rm, __shfl_xor_sync(0xffffffffu, rm, 1, 8));
            rm = fmaxf(rm, __shfl_xor_sync(0xffffffffu, rm, 2, 8));
            rm = fmaxf(rm, __shfl_xor_sync(0xffffffffu, rm, 4, 8));
            const float mn = fmaxf(m_i[i], rm);
            const float alpha = __expf(m_i[i] - mn);
            float rs = 0.f;
#pragma unroll
            for (int j = 0; j < 4; j++) {
                s[i][j] = __expf(s[i][j] - mn);
                rs += s[i][j];
            }
            rs += __shfl_xor_sync(0xffffffffu, rs, 1, 8);
            rs += __shfl_xor_sync(0xffffffffu, rs, 2, 8);
            rs += __shfl_xor_sync(0xffffffffu, rs, 4, 8);
            l_i[i] = l_i[i] * alpha + rs;
            m_i[i] = mn;
#pragma unroll
            for (int j = 0; j < 8; j++) acc[i][j] *= alpha;
#pragma unroll
            for (int j = 0; j < 4; j++) ps[ty * 4 + i][tx * 4 + j] = s[i][j];
        }
        __syncthreads();

#pragma unroll 4
        for (int kk = 0; kk < 32; kk++) {
            float p[4], v[8];
#pragma unroll
            for (int i = 0; i < 4; i++) p[i] = ps[ty * 4 + i][kk];
#pragma unroll
            for (int j = 0; j < 8; j++) v[j] = vs[kk][tx * 8 + j];
#pragma unroll
            for (int i = 0; i < 4; i++)
#pragma unroll
                for (int j = 0; j < 8; j++)
                    acc[i][j] = fmaf(p[i], v[j], acc[i][j]);
        }
    }

#pragma unroll
    for (int i = 0; i < 4; i++) {
        const float inv = 1.0f / l_i[i];
        float4 o0, o1;
        o0.x = acc[i][0] * inv; o0.y = acc[i][1] * inv;
        o0.z = acc[i][2] * inv; o0.w = acc[i][3] * inv;
        o1.x = acc[i][4] * inv; o1.y = acc[i][5] * inv;
        o1.z = acc[i][6] * inv; o1.w = acc[i][7] * inv;
        const size_t orow = base + (size_t)(q0 + ty * 4 + i) * DIM + tx * 8;
        *(float4*)(Op + orow)     = o0;
        *(float4*)(Op + orow + 4) = o1;
    }
}

// ---------------------------------------------------------------------------
// Launch
// ---------------------------------------------------------------------------
extern "C" void kernel_launch(void* const* d_in, const int* in_sizes, int n_in,
                              void* d_out, int out_size) {
    (void)in_sizes; (void)n_in; (void)out_size;
    const float* Q     = (const float*)d_in[0];
    const float* K     = (const float*)d_in[1];
    const float* V     = (const float*)d_in[2];
    const float* Wq    = (const float*)d_in[3];
    const float* Wk    = (const float*)d_in[4];
    const float* Wv    = (const float*)d_in[5];
    const float* Wo    = (const float*)d_in[6];
    const float* pre_g = (const float*)d_in[7];
    const float* pre_b = (const float*)d_in[8];
    const float* ln_g  = (const float*)d_in[9];
    const float* ln_b  = (const float*)d_in[10];
    float* out = (float*)d_out;

    __nv_bfloat16 *qh, *ql, *kh, *kl, *vh, *vl, *xh, *xl;
    __nv_bfloat16 *wqh, *wql, *wkh, *wkl, *wvh, *wvl, *woh, *wol;
    float *qp, *kp, *vp, *op, *xp;
    cudaGetSymbolAddress((void**)&qh,  g_Qh);
    cudaGetSymbolAddress((void**)&ql,  g_Ql);
    cudaGetSymbolAddress((void**)&kh,  g_Kh);
    cudaGetSymbolAddress((void**)&kl,  g_Kl);
    cudaGetSymbolAddress((void**)&vh,  g_Vh);
    cudaGetSymbolAddress((void**)&vl,  g_Vl);
    cudaGetSymbolAddress((void**)&xh,  g_Xh);
    cudaGetSymbolAddress((void**)&xl,  g_Xl);
    cudaGetSymbolAddress((void**)&wqh, g_Wqh);
    cudaGetSymbolAddress((void**)&wql, g_Wql);
    cudaGetSymbolAddress((void**)&wkh, g_Wkh);
    cudaGetSymbolAddress((void**)&wkl, g_Wkl);
    cudaGetSymbolAddress((void**)&wvh, g_Wvh);
    cudaGetSymbolAddress((void**)&wvl, g_Wvl);
    cudaGetSymbolAddress((void**)&woh, g_Woh);
    cudaGetSymbolAddress((void**)&wol, g_Wol);
    cudaGetSymbolAddress((void**)&qp,  g_q);
    cudaGetSymbolAddress((void**)&kp,  g_k);
    cudaGetSymbolAddress((void**)&vp,  g_v);
    cudaGetSymbolAddress((void**)&op,  g_O);
    cudaGetSymbolAddress((void**)&xp,  g_X);

    static int attr_set = 0;
    if (!attr_set) {
        cudaFuncSetAttribute(gemm_mma3, cudaFuncAttributeMaxDynamicSharedMemorySize, GSMEM);
        attr_set = 1;
    }

    const dim3 ggrid(DIM / GBN, MROWS / GBM);  // (8, 32)

    // weight + V split conversions
    f2bf_split_kernel<<<DIM * DIM / 1024, 256>>>(Wq, wqh, wql);
    f2bf_split_kernel<<<DIM * DIM / 1024, 256>>>(Wk, wkh, wkl);
    f2bf_split_kernel<<<DIM * DIM / 1024, 256>>>(Wv, wvh, wvl);
    f2bf_split_kernel<<<DIM * DIM / 1024, 256>>>(Wo, woh, wol);
    f2bf_split_kernel<<<(size_t)MROWS * DIM / 1024, 256>>>(V, vh, vl);

    ln_split_kernel<<<MROWS, 256>>>(Q, qh, ql, nullptr, pre_g, pre_b);
    ln_split_kernel<<<MROWS, 256>>>(K, kh, kl, nullptr, pre_g, pre_b);

    gemm_mma3<<<ggrid, 256, GSMEM>>>(qh, ql, wqh, wql, qp, nullptr, 0);
    gemm_mma3<<<ggrid, 256, GSMEM>>>(kh, kl, wkh, wkl, kp, nullptr, 0);
    gemm_mma3<<<ggrid, 256, GSMEM>>>(vh, vl, wvh, wvl, vp, nullptr, 0);

    attn_kernel<<<dim3(SEQ / 64, NH, NB), 128>>>(qp, kp, vp, op);

    ln_split_kernel<<<MROWS, 256>>>(op, xh, xl, xp, ln_g, ln_b);
    gemm_mma3<<<ggrid, 256, GSMEM>>>(xh, xl, woh, wol, out, xp, 1);
}